// round 14
// baseline (speedup 1.0000x reference)
#include <cuda_runtime.h>
#include <cuda_fp16.h>

#define MAX_N 100000
#define MAX_E 1600000
#define D 64
#define CAT_STRIDE 192  // 3*D
#define STILE 1024
#define MAX_TILES ((MAX_N + STILE - 1) / STILE)
#define NPB 64
#define XT_STRIDE 68

typedef unsigned long long u64;

// Scratch (device globals; zero-initialized at load, re-zeroed by tail kernel)
__device__ int      g_deg_out[MAX_N];
__device__ int      g_deg_in[MAX_N];
__device__ unsigned g_status[MAX_TILES];
__device__ int2     g_rowinfo[MAX_N];    // (row start, deg_in)
__device__ int      g_cursor[MAX_N];
__device__ int      g_csr[MAX_E];        // plain src index
__device__ float    g_agg[MAX_N * D];
__device__ __half2  g_xh[MAX_N * 32];    // fp16 mirror, PRE-SCALED by inv_out

// ---------------------------------------------------------------------------
// f32x2 packed helpers (sm_10x)
__device__ __forceinline__ u64 pk2(float a, float b) {
    u64 r; asm("mov.b64 %0, {%1, %2};" : "=l"(r) : "f"(a), "f"(b)); return r;
}
__device__ __forceinline__ u64 fma2(u64 a, u64 b, u64 c) {
    u64 d; asm("fma.rn.f32x2 %0, %1, %2, %3;" : "=l"(d) : "l"(a), "l"(b), "l"(c)); return d;
}
__device__ __forceinline__ float2 up2(u64 a) {
    float2 f; asm("mov.b64 {%0, %1}, %2;" : "=f"(f.x), "=f"(f.y) : "l"(a)); return f;
}

// ---------------------------------------------------------------------------
// Count both degrees in one edge pass.
__global__ void deg_count_kernel(const int* __restrict__ src, const int* __restrict__ dst,
                                 int* __restrict__ dout, int* __restrict__ din, int e) {
    int i = blockIdx.x * blockDim.x + threadIdx.x;
    if (i < e) {
        atomicAdd(&dout[src[i]], 1);
        atomicAdd(&din[dst[i]], 1);
    }
}

// Single-pass scan with decoupled lookback (98 tiles < 148 SMs -> all resident).
__global__ void __launch_bounds__(256)
scan_kernel(const int* __restrict__ deg, unsigned* __restrict__ status,
            int2* __restrict__ rowinfo, int* __restrict__ cursor, int n) {
    __shared__ int wsums[8];
    __shared__ int s_excl;

    int tid = threadIdx.x, lane = tid & 31, w = tid >> 5;
    int base = blockIdx.x * STILE + tid * 4;

    int d0 = 0, d1 = 0, d2 = 0, d3 = 0;
    if (base + 3 < n) {
        int4 v = *reinterpret_cast<const int4*>(deg + base);
        d0 = v.x; d1 = v.y; d2 = v.z; d3 = v.w;
    } else {
        if (base + 0 < n) d0 = deg[base + 0];
        if (base + 1 < n) d1 = deg[base + 1];
        if (base + 2 < n) d2 = deg[base + 2];
        if (base + 3 < n) d3 = deg[base + 3];
    }
    int s = d0 + d1 + d2 + d3;

    int inc = s;
    #pragma unroll
    for (int o = 1; o < 32; o <<= 1) {
        int t = __shfl_up_sync(0xffffffffu, inc, o);
        if (lane >= o) inc += t;
    }
    if (lane == 31) wsums[w] = inc;
    __syncthreads();
    if (w == 0 && lane < 8) {
        int t = wsums[lane];
        #pragma unroll
        for (int o = 1; o < 8; o <<= 1) {
            int u = __shfl_up_sync(0xffu, t, o);
            if (lane >= o) t += u;
        }
        wsums[lane] = t;
    }
    __syncthreads();
    int local_excl  = (inc - s) + (w > 0 ? wsums[w - 1] : 0);
    int block_total = wsums[7];

    if (w == 0) {
        volatile unsigned* vst = status;
        if (blockIdx.x == 0) {
            if (lane == 0) {
                vst[0] = 0x80000000u | (unsigned)block_total;
                s_excl = 0;
            }
        } else {
            if (lane == 0) vst[blockIdx.x] = 0x40000000u | (unsigned)block_total;
            int acc = 0;
            int t_hi = blockIdx.x - 1;
            bool done = false;
            while (!done) {
                int idx = t_hi - lane;
                unsigned sv;
                do {
                    sv = (idx >= 0) ? vst[idx] : 0x80000000u;
                } while (__any_sync(0xffffffffu, (sv >> 30) == 0));
                unsigned pm = __ballot_sync(0xffffffffu, (sv >> 30) == 2u);
                int val = (int)(sv & 0x3FFFFFFFu);
                int take;
                if (pm) {
                    int plane = __ffs(pm) - 1;
                    take = (lane <= plane) ? val : 0;
                    done = true;
                } else {
                    take = (idx >= 0) ? val : 0;
                    t_hi -= 32;
                }
                #pragma unroll
                for (int o = 16; o; o >>= 1)
                    take += __shfl_xor_sync(0xffffffffu, take, o);
                acc += take;
            }
            if (lane == 0) {
                vst[blockIdx.x] = 0x80000000u | (unsigned)(acc + block_total);
                s_excl = acc;
            }
        }
    }
    __syncthreads();

    int run = s_excl + local_excl;
    if (base + 3 < n) {
        int r0 = run, r1 = r0 + d0, r2 = r1 + d1, r3 = r2 + d2;
        int4* ri = reinterpret_cast<int4*>(rowinfo + base);
        ri[0] = make_int4(r0, d0, r1, d1);
        ri[1] = make_int4(r2, d2, r3, d3);
        *reinterpret_cast<int4*>(cursor + base) = make_int4(r0, r1, r2, r3);
    } else {
        int d[4] = { d0, d1, d2, d3 };
        for (int jj = 0; jj < 4; ++jj) {
            int i = base + jj;
            if (i < n) { rowinfo[i] = make_int2(run, d[jj]); cursor[i] = run; }
            run += d[jj];
        }
    }
}

// Merged place + prescale: first eb blocks place edges into CSR slots,
// remaining blocks prescale node_feat into the fp16 mirror.
__global__ void __launch_bounds__(256)
place_prescale_kernel(const int* __restrict__ src, const int* __restrict__ dst,
                      int* __restrict__ cursor, int* __restrict__ csr, int e, int eb,
                      const float4* __restrict__ x, const int* __restrict__ deg_out,
                      uint4* __restrict__ xh, int m8) {
    int bid = blockIdx.x;
    if (bid < eb) {
        int i = bid * blockDim.x + threadIdx.x;
        if (i < e) {
            int p = atomicAdd(&cursor[dst[i]], 1);
            csr[p] = src[i];
        }
    } else {
        int i = (bid - eb) * blockDim.x + threadIdx.x;  // one 8-float group / thread
        if (i < m8) {
            int node = i >> 3;
            float so = rsqrtf((float)max(__ldg(&deg_out[node]), 1));
            float4 v0 = x[2 * i];
            float4 v1 = x[2 * i + 1];
            __half2 h0 = __floats2half2_rn(v0.x * so, v0.y * so);
            __half2 h1 = __floats2half2_rn(v0.z * so, v0.w * so);
            __half2 h2 = __floats2half2_rn(v1.x * so, v1.y * so);
            __half2 h3 = __floats2half2_rn(v1.z * so, v1.w * so);
            uint4 o;
            o.x = *reinterpret_cast<unsigned*>(&h0);
            o.y = *reinterpret_cast<unsigned*>(&h1);
            o.z = *reinterpret_cast<unsigned*>(&h2);
            o.w = *reinterpret_cast<unsigned*>(&h3);
            xh[i] = o;
        }
    }
}

// ---------------------------------------------------------------------------
// Gather: one warp per node; 4 edges per warp-instruction group; 16 edges/iter.
// Pairwise fp16 adds halve the cvt+FADD stream (error ~2^-11 per pair, safe).
__global__ void __launch_bounds__(256)
gather_kernel(const __half2* __restrict__ xh,
              const int2* __restrict__ rowinfo,
              const int* __restrict__ csr,
              float4* __restrict__ agg, int n) {
    int node = (blockIdx.x * blockDim.x + threadIdx.x) >> 5;
    int lane = threadIdx.x & 31;
    if (node >= n) return;

    int sub   = lane >> 3;
    int chunk = lane & 7;

    int2 ri   = rowinfo[node];
    int  j    = ri.x;
    int  rend = ri.x + ri.y;

    const uint4* __restrict__ xv = reinterpret_cast<const uint4*>(xh);

    float a0 = 0.f, a1 = 0.f, a2 = 0.f, a3 = 0.f;
    float a4 = 0.f, a5 = 0.f, a6 = 0.f, a7 = 0.f;

    // fp32 accumulate one uint4 (4 half2)
    auto accum = [&](uint4 d) {
        float2 f0 = __half22float2(*reinterpret_cast<__half2*>(&d.x));
        float2 f1 = __half22float2(*reinterpret_cast<__half2*>(&d.y));
        float2 f2 = __half22float2(*reinterpret_cast<__half2*>(&d.z));
        float2 f3 = __half22float2(*reinterpret_cast<__half2*>(&d.w));
        a0 += f0.x; a1 += f0.y;
        a2 += f1.x; a3 += f1.y;
        a4 += f2.x; a5 += f2.y;
        a6 += f3.x; a7 += f3.y;
    };
    // pair two edges in fp16, then fp32 accumulate the pair-sum
    auto accum2 = [&](uint4 da, uint4 db) {
        __half2 s0 = __hadd2(*reinterpret_cast<__half2*>(&da.x),
                             *reinterpret_cast<__half2*>(&db.x));
        __half2 s1 = __hadd2(*reinterpret_cast<__half2*>(&da.y),
                             *reinterpret_cast<__half2*>(&db.y));
        __half2 s2 = __hadd2(*reinterpret_cast<__half2*>(&da.z),
                             *reinterpret_cast<__half2*>(&db.z));
        __half2 s3 = __hadd2(*reinterpret_cast<__half2*>(&da.w),
                             *reinterpret_cast<__half2*>(&db.w));
        float2 f0 = __half22float2(s0);
        float2 f1 = __half22float2(s1);
        float2 f2 = __half22float2(s2);
        float2 f3 = __half22float2(s3);
        a0 += f0.x; a1 += f0.y;
        a2 += f1.x; a3 += f1.y;
        a4 += f2.x; a5 += f2.y;
        a6 += f3.x; a7 += f3.y;
    };

    // 16 edges per iter: 4 independent row LDG.128 in flight
    for (; j + 16 <= rend; j += 16) {
        int s0 = csr[j +      sub];
        int s1 = csr[j +  4 + sub];
        int s2 = csr[j +  8 + sub];
        int s3 = csr[j + 12 + sub];
        uint4 d0 = xv[(long)s0 * 8 + chunk];
        uint4 d1 = xv[(long)s1 * 8 + chunk];
        uint4 d2 = xv[(long)s2 * 8 + chunk];
        uint4 d3 = xv[(long)s3 * 8 + chunk];
        accum2(d0, d1);
        accum2(d2, d3);
    }
    for (; j + 8 <= rend; j += 8) {
        int s0 = csr[j + sub];
        int s1 = csr[j + 4 + sub];
        uint4 d0 = xv[(long)s0 * 8 + chunk];
        uint4 d1 = xv[(long)s1 * 8 + chunk];
        accum2(d0, d1);
    }
    for (; j < rend; j += 4) {
        int ei = j + sub;
        if (ei < rend) {
            int s = csr[ei];
            uint4 d = xv[(long)s * 8 + chunk];
            accum(d);
        }
    }

    #pragma unroll
    for (int o = 8; o <= 16; o <<= 1) {
        a0 += __shfl_xor_sync(0xffffffffu, a0, o);
        a1 += __shfl_xor_sync(0xffffffffu, a1, o);
        a2 += __shfl_xor_sync(0xffffffffu, a2, o);
        a3 += __shfl_xor_sync(0xffffffffu, a3, o);
        a4 += __shfl_xor_sync(0xffffffffu, a4, o);
        a5 += __shfl_xor_sync(0xffffffffu, a5, o);
        a6 += __shfl_xor_sync(0xffffffffu, a6, o);
        a7 += __shfl_xor_sync(0xffffffffu, a7, o);
    }
    if (sub == 0) {
        float4* ao = agg + (long)node * 16 + 2 * chunk;
        ao[0] = make_float4(a0, a1, a2, a3);
        ao[1] = make_float4(a4, a5, a6, a7);
    }
}

// ---------------------------------------------------------------------------
// GEMM: y = relu((agg * rsqrt(deg_in)) @ W + b)
// fp16 mirror epilogue writes y * rsqrt(deg_out) when xh_out != null.
__global__ void __launch_bounds__(256)
gemm_kernel(const float* __restrict__ agg, const int* __restrict__ deg_in,
            const int* __restrict__ deg_out,
            const float* __restrict__ W, const float* __restrict__ b,
            float* __restrict__ cat_out, float* __restrict__ pool_out,
            __half2* __restrict__ xh_out, int n) {
    __shared__ float  xs_t[D * XT_STRIDE];
    __shared__ float4 Ws4[D * 16];
    __shared__ float  bs[D];

    int tid  = threadIdx.x;
    int base = blockIdx.x * NPB;

    const float4* W4 = reinterpret_cast<const float4*>(W);
    #pragma unroll
    for (int r = 0; r < 4; ++r)
        Ws4[tid + 256 * r] = W4[tid + 256 * r];
    if (tid < D) bs[tid] = b[tid];

    {
        int node = base + (tid >> 2);
        int k16  = tid & 3;
        if (node < n) {
            float si = rsqrtf((float)max(__ldg(&deg_in[node]), 1));
            const float4* af = reinterpret_cast<const float4*>(agg) + (long)node * 16;
            #pragma unroll
            for (int i = 0; i < 4; ++i) {
                float4 v = af[k16 * 4 + i];
                int k = k16 * 16 + i * 4;
                xs_t[(k + 0) * XT_STRIDE + (node - base)] = v.x * si;
                xs_t[(k + 1) * XT_STRIDE + (node - base)] = v.y * si;
                xs_t[(k + 2) * XT_STRIDE + (node - base)] = v.z * si;
                xs_t[(k + 3) * XT_STRIDE + (node - base)] = v.w * si;
            }
        }
    }
    __syncthreads();

    int c4 = tid & 15;
    int ng = tid >> 4;

    u64 acc[4][2];
    {
        u64 blo = pk2(bs[4 * c4 + 0], bs[4 * c4 + 1]);
        u64 bhi = pk2(bs[4 * c4 + 2], bs[4 * c4 + 3]);
        #pragma unroll
        for (int i = 0; i < 4; ++i) { acc[i][0] = blo; acc[i][1] = bhi; }
    }

    #pragma unroll 4
    for (int k = 0; k < D; ++k) {
        float4 w = Ws4[k * 16 + c4];
        u64 wlo = pk2(w.x, w.y);
        u64 whi = pk2(w.z, w.w);
        float4 xv = *reinterpret_cast<const float4*>(&xs_t[k * XT_STRIDE + 4 * ng]);
        u64 x0 = pk2(xv.x, xv.x);
        u64 x1 = pk2(xv.y, xv.y);
        u64 x2 = pk2(xv.z, xv.z);
        u64 x3 = pk2(xv.w, xv.w);
        acc[0][0] = fma2(x0, wlo, acc[0][0]); acc[0][1] = fma2(x0, whi, acc[0][1]);
        acc[1][0] = fma2(x1, wlo, acc[1][0]); acc[1][1] = fma2(x1, whi, acc[1][1]);
        acc[2][0] = fma2(x2, wlo, acc[2][0]); acc[2][1] = fma2(x2, whi, acc[2][1]);
        acc[3][0] = fma2(x3, wlo, acc[3][0]); acc[3][1] = fma2(x3, whi, acc[3][1]);
    }

    float psum[4];
    #pragma unroll
    for (int i = 0; i < 4; ++i) {
        float2 lo = up2(acc[i][0]);
        float2 hi = up2(acc[i][1]);
        float v0 = fmaxf(lo.x, 0.f), v1 = fmaxf(lo.y, 0.f);
        float v2 = fmaxf(hi.x, 0.f), v3 = fmaxf(hi.y, 0.f);
        psum[i] = (v0 + v1) + (v2 + v3);
        int node = base + 4 * ng + i;
        if (node < n) {
            *reinterpret_cast<float4*>(cat_out + (long)node * CAT_STRIDE + 4 * c4)
                = make_float4(v0, v1, v2, v3);
            if (xh_out) {
                float so = rsqrtf((float)max(__ldg(&deg_out[node]), 1));
                xh_out[(long)node * 32 + 2 * c4]     = __floats2half2_rn(v0 * so, v1 * so);
                xh_out[(long)node * 32 + 2 * c4 + 1] = __floats2half2_rn(v2 * so, v3 * so);
            }
        }
    }
    #pragma unroll
    for (int o = 1; o < 16; o <<= 1) {
        #pragma unroll
        for (int i = 0; i < 4; ++i)
            psum[i] += __shfl_xor_sync(0xffffffffu, psum[i], o);
    }
    if (c4 == 0) {
        #pragma unroll
        for (int i = 0; i < 4; ++i) {
            int node = base + 4 * ng + i;
            if (node < n) pool_out[node] = psum[i];
        }
    }
}

// Tail: reset accumulators for the next graph replay.
__global__ void zero_tail_kernel(int* __restrict__ a, int* __restrict__ b,
                                 unsigned* __restrict__ st, int n, int ntiles) {
    int i = blockIdx.x * blockDim.x + threadIdx.x;
    if (i < n) { a[i] = 0; b[i] = 0; }
    if (i < ntiles) st[i] = 0u;
}

// ---------------------------------------------------------------------------
extern "C" void kernel_launch(void* const* d_in, const int* in_sizes, int n_in,
                              void* d_out, int out_size) {
    const float* node_feat = (const float*)d_in[0];
    const int*   src       = (const int*)  d_in[1];
    const int*   dst       = (const int*)  d_in[2];
    const float* W[3] = { (const float*)d_in[4], (const float*)d_in[6], (const float*)d_in[8] };
    const float* B[3] = { (const float*)d_in[5], (const float*)d_in[7], (const float*)d_in[9] };

    const int n = in_sizes[0] / D;
    const int e = in_sizes[1];

    float* out = (float*)d_out;
    float* pool_base = out;                 // [3n]
    float* cat_base  = out + 3 * (long)n;   // [n, 192]

    int *deg_out, *deg_in, *cursor, *csr;
    int2 *rowinfo;
    unsigned* status;
    float* agg;
    __half2* xh;
    cudaGetSymbolAddress((void**)&deg_out, g_deg_out);
    cudaGetSymbolAddress((void**)&deg_in,  g_deg_in);
    cudaGetSymbolAddress((void**)&status,  g_status);
    cudaGetSymbolAddress((void**)&rowinfo, g_rowinfo);
    cudaGetSymbolAddress((void**)&cursor,  g_cursor);
    cudaGetSymbolAddress((void**)&csr,     g_csr);
    cudaGetSymbolAddress((void**)&agg,     g_agg);
    cudaGetSymbolAddress((void**)&xh,      g_xh);

    const int T = 256;
    const int ntiles = (n + STILE - 1) / STILE;
    const int eb = (e + T - 1) / T;
    const int pb = (n * 8 + T - 1) / T;

    // CSR build: deg_count(0) -> scan(1) -> place+prescale(2)
    deg_count_kernel<<<eb, T>>>(src, dst, deg_out, deg_in, e);
    scan_kernel<<<ntiles, T>>>(deg_in, status, rowinfo, cursor, n);
    place_prescale_kernel<<<eb + pb, T>>>(src, dst, cursor, csr, e, eb,
                                          (const float4*)node_feat, deg_out,
                                          (uint4*)xh, n * 8);

    // 3 layers: gather(3,5,7) -> gemm(4,6,8)
    const int gather_blocks = (n * 32 + T - 1) / T;
    const int gemm_blocks   = (n + NPB - 1) / NPB;

    gather_kernel<<<gather_blocks, T>>>(xh, rowinfo, csr, (float4*)agg, n);
    gemm_kernel<<<gemm_blocks, T>>>(agg, deg_in, deg_out, W[0], B[0],
                                    cat_base + 0 * D, pool_base + 0L * n, xh, n);
    gather_kernel<<<gather_blocks, T>>>(xh, rowinfo, csr, (float4*)agg, n);
    gemm_kernel<<<gemm_blocks, T>>>(agg, deg_in, deg_out, W[1], B[1],
                                    cat_base + 1 * D, pool_base + 1L * n, xh, n);
    gather_kernel<<<gather_blocks, T>>>(xh, rowinfo, csr, (float4*)agg, n);
    gemm_kernel<<<gemm_blocks, T>>>(agg, deg_in, deg_out, W[2], B[2],
                                    cat_base + 2 * D, pool_base + 2L * n,
                                    (__half2*)nullptr, n);

    // reset for next replay
    zero_tail_kernel<<<(n + T - 1) / T, T>>>(deg_out, deg_in, status, n, ntiles);
}

// round 15
// speedup vs baseline: 1.1336x; 1.1336x over previous
#include <cuda_runtime.h>
#include <cuda_fp16.h>

#define MAX_N 100000
#define MAX_E 1600000
#define D 64
#define CAT_STRIDE 192  // 3*D
#define STILE 1024
#define MAX_TILES ((MAX_N + STILE - 1) / STILE)
#define NPB 64
#define XT_STRIDE 68

typedef unsigned long long u64;

// Scratch (device globals; zero-initialized at load; deg/status re-zeroed by
// the final gemm each replay; everything else fully overwritten per replay)
__device__ int      g_deg_out[MAX_N];
__device__ int      g_deg_in[MAX_N];
__device__ unsigned g_status[MAX_TILES];
__device__ int2     g_rowinfo[MAX_N];    // (row start, deg_in)
__device__ int      g_cursor[MAX_N];
__device__ int      g_csr[MAX_E];        // plain src index
__device__ float    g_agg[MAX_N * D];
__device__ __half2  g_xh[MAX_N * 32];    // fp16 mirror, PRE-SCALED by inv_out

// ---------------------------------------------------------------------------
// f32x2 packed helpers (sm_10x)
__device__ __forceinline__ u64 pk2(float a, float b) {
    u64 r; asm("mov.b64 %0, {%1, %2};" : "=l"(r) : "f"(a), "f"(b)); return r;
}
__device__ __forceinline__ u64 fma2(u64 a, u64 b, u64 c) {
    u64 d; asm("fma.rn.f32x2 %0, %1, %2, %3;" : "=l"(d) : "l"(a), "l"(b), "l"(c)); return d;
}
__device__ __forceinline__ float2 up2(u64 a) {
    float2 f; asm("mov.b64 {%0, %1}, %2;" : "=f"(f.x), "=f"(f.y) : "l"(a)); return f;
}

// ---------------------------------------------------------------------------
// Count both degrees in one edge pass.
__global__ void deg_count_kernel(const int* __restrict__ src, const int* __restrict__ dst,
                                 int* __restrict__ dout, int* __restrict__ din, int e) {
    int i = blockIdx.x * blockDim.x + threadIdx.x;
    if (i < e) {
        atomicAdd(&dout[src[i]], 1);
        atomicAdd(&din[dst[i]], 1);
    }
}

// Single-pass scan with decoupled lookback (98 tiles < 148 SMs -> all resident).
__global__ void __launch_bounds__(256)
scan_kernel(const int* __restrict__ deg, unsigned* __restrict__ status,
            int2* __restrict__ rowinfo, int* __restrict__ cursor, int n) {
    __shared__ int wsums[8];
    __shared__ int s_excl;

    int tid = threadIdx.x, lane = tid & 31, w = tid >> 5;
    int base = blockIdx.x * STILE + tid * 4;

    int d0 = 0, d1 = 0, d2 = 0, d3 = 0;
    if (base + 3 < n) {
        int4 v = *reinterpret_cast<const int4*>(deg + base);
        d0 = v.x; d1 = v.y; d2 = v.z; d3 = v.w;
    } else {
        if (base + 0 < n) d0 = deg[base + 0];
        if (base + 1 < n) d1 = deg[base + 1];
        if (base + 2 < n) d2 = deg[base + 2];
        if (base + 3 < n) d3 = deg[base + 3];
    }
    int s = d0 + d1 + d2 + d3;

    int inc = s;
    #pragma unroll
    for (int o = 1; o < 32; o <<= 1) {
        int t = __shfl_up_sync(0xffffffffu, inc, o);
        if (lane >= o) inc += t;
    }
    if (lane == 31) wsums[w] = inc;
    __syncthreads();
    if (w == 0 && lane < 8) {
        int t = wsums[lane];
        #pragma unroll
        for (int o = 1; o < 8; o <<= 1) {
            int u = __shfl_up_sync(0xffu, t, o);
            if (lane >= o) t += u;
        }
        wsums[lane] = t;
    }
    __syncthreads();
    int local_excl  = (inc - s) + (w > 0 ? wsums[w - 1] : 0);
    int block_total = wsums[7];

    if (w == 0) {
        volatile unsigned* vst = status;
        if (blockIdx.x == 0) {
            if (lane == 0) {
                vst[0] = 0x80000000u | (unsigned)block_total;
                s_excl = 0;
            }
        } else {
            if (lane == 0) vst[blockIdx.x] = 0x40000000u | (unsigned)block_total;
            int acc = 0;
            int t_hi = blockIdx.x - 1;
            bool done = false;
            while (!done) {
                int idx = t_hi - lane;
                unsigned sv;
                do {
                    sv = (idx >= 0) ? vst[idx] : 0x80000000u;
                } while (__any_sync(0xffffffffu, (sv >> 30) == 0));
                unsigned pm = __ballot_sync(0xffffffffu, (sv >> 30) == 2u);
                int val = (int)(sv & 0x3FFFFFFFu);
                int take;
                if (pm) {
                    int plane = __ffs(pm) - 1;
                    take = (lane <= plane) ? val : 0;
                    done = true;
                } else {
                    take = (idx >= 0) ? val : 0;
                    t_hi -= 32;
                }
                #pragma unroll
                for (int o = 16; o; o >>= 1)
                    take += __shfl_xor_sync(0xffffffffu, take, o);
                acc += take;
            }
            if (lane == 0) {
                vst[blockIdx.x] = 0x80000000u | (unsigned)(acc + block_total);
                s_excl = acc;
            }
        }
    }
    __syncthreads();

    int run = s_excl + local_excl;
    if (base + 3 < n) {
        int r0 = run, r1 = r0 + d0, r2 = r1 + d1, r3 = r2 + d2;
        int4* ri = reinterpret_cast<int4*>(rowinfo + base);
        ri[0] = make_int4(r0, d0, r1, d1);
        ri[1] = make_int4(r2, d2, r3, d3);
        *reinterpret_cast<int4*>(cursor + base) = make_int4(r0, r1, r2, r3);
    } else {
        int d[4] = { d0, d1, d2, d3 };
        for (int jj = 0; jj < 4; ++jj) {
            int i = base + jj;
            if (i < n) { rowinfo[i] = make_int2(run, d[jj]); cursor[i] = run; }
            run += d[jj];
        }
    }
}

// Merged place + prescale: first eb blocks place edges into CSR slots,
// remaining blocks prescale node_feat into the fp16 mirror.
__global__ void __launch_bounds__(256)
place_prescale_kernel(const int* __restrict__ src, const int* __restrict__ dst,
                      int* __restrict__ cursor, int* __restrict__ csr, int e, int eb,
                      const float4* __restrict__ x, const int* __restrict__ deg_out,
                      uint4* __restrict__ xh, int m8) {
    int bid = blockIdx.x;
    if (bid < eb) {
        int i = bid * blockDim.x + threadIdx.x;
        if (i < e) {
            int p = atomicAdd(&cursor[dst[i]], 1);
            csr[p] = src[i];
        }
    } else {
        int i = (bid - eb) * blockDim.x + threadIdx.x;  // one 8-float group / thread
        if (i < m8) {
            int node = i >> 3;
            float so = rsqrtf((float)max(__ldg(&deg_out[node]), 1));
            float4 v0 = x[2 * i];
            float4 v1 = x[2 * i + 1];
            __half2 h0 = __floats2half2_rn(v0.x * so, v0.y * so);
            __half2 h1 = __floats2half2_rn(v0.z * so, v0.w * so);
            __half2 h2 = __floats2half2_rn(v1.x * so, v1.y * so);
            __half2 h3 = __floats2half2_rn(v1.z * so, v1.w * so);
            uint4 o;
            o.x = *reinterpret_cast<unsigned*>(&h0);
            o.y = *reinterpret_cast<unsigned*>(&h1);
            o.z = *reinterpret_cast<unsigned*>(&h2);
            o.w = *reinterpret_cast<unsigned*>(&h3);
            xh[i] = o;
        }
    }
}

// ---------------------------------------------------------------------------
// Gather: one warp per node; 4 edges per warp-instruction group.
// 8-edge unroll with pairwise fp16 adds; __launch_bounds__(256,8) caps regs
// at 32 so occupancy stays full (round-14 lesson: occupancy >= op count).
__global__ void __launch_bounds__(256, 8)
gather_kernel(const __half2* __restrict__ xh,
              const int2* __restrict__ rowinfo,
              const int* __restrict__ csr,
              float4* __restrict__ agg, int n) {
    int node = (blockIdx.x * blockDim.x + threadIdx.x) >> 5;
    int lane = threadIdx.x & 31;
    if (node >= n) return;

    int sub   = lane >> 3;
    int chunk = lane & 7;

    int2 ri   = rowinfo[node];
    int  j    = ri.x;
    int  rend = ri.x + ri.y;

    const uint4* __restrict__ xv = reinterpret_cast<const uint4*>(xh);

    float a0 = 0.f, a1 = 0.f, a2 = 0.f, a3 = 0.f;
    float a4 = 0.f, a5 = 0.f, a6 = 0.f, a7 = 0.f;

    // fp32 accumulate one uint4 (4 half2)
    auto accum = [&](uint4 d) {
        float2 f0 = __half22float2(*reinterpret_cast<__half2*>(&d.x));
        float2 f1 = __half22float2(*reinterpret_cast<__half2*>(&d.y));
        float2 f2 = __half22float2(*reinterpret_cast<__half2*>(&d.z));
        float2 f3 = __half22float2(*reinterpret_cast<__half2*>(&d.w));
        a0 += f0.x; a1 += f0.y;
        a2 += f1.x; a3 += f1.y;
        a4 += f2.x; a5 += f2.y;
        a6 += f3.x; a7 += f3.y;
    };
    // pair two edges in fp16, then fp32 accumulate the pair-sum
    auto accum2 = [&](uint4 da, uint4 db) {
        __half2 s0 = __hadd2(*reinterpret_cast<__half2*>(&da.x),
                             *reinterpret_cast<__half2*>(&db.x));
        __half2 s1 = __hadd2(*reinterpret_cast<__half2*>(&da.y),
                             *reinterpret_cast<__half2*>(&db.y));
        __half2 s2 = __hadd2(*reinterpret_cast<__half2*>(&da.z),
                             *reinterpret_cast<__half2*>(&db.z));
        __half2 s3 = __hadd2(*reinterpret_cast<__half2*>(&da.w),
                             *reinterpret_cast<__half2*>(&db.w));
        float2 f0 = __half22float2(s0);
        float2 f1 = __half22float2(s1);
        float2 f2 = __half22float2(s2);
        float2 f3 = __half22float2(s3);
        a0 += f0.x; a1 += f0.y;
        a2 += f1.x; a3 += f1.y;
        a4 += f2.x; a5 += f2.y;
        a6 += f3.x; a7 += f3.y;
    };

    // 8 edges per iter: 2 independent row LDG.128 in flight, 2 uint4 live
    for (; j + 8 <= rend; j += 8) {
        int s0 = csr[j + sub];
        int s1 = csr[j + 4 + sub];
        uint4 d0 = xv[(long)s0 * 8 + chunk];
        uint4 d1 = xv[(long)s1 * 8 + chunk];
        accum2(d0, d1);
    }
    for (; j < rend; j += 4) {
        int ei = j + sub;
        if (ei < rend) {
            int s = csr[ei];
            uint4 d = xv[(long)s * 8 + chunk];
            accum(d);
        }
    }

    #pragma unroll
    for (int o = 8; o <= 16; o <<= 1) {
        a0 += __shfl_xor_sync(0xffffffffu, a0, o);
        a1 += __shfl_xor_sync(0xffffffffu, a1, o);
        a2 += __shfl_xor_sync(0xffffffffu, a2, o);
        a3 += __shfl_xor_sync(0xffffffffu, a3, o);
        a4 += __shfl_xor_sync(0xffffffffu, a4, o);
        a5 += __shfl_xor_sync(0xffffffffu, a5, o);
        a6 += __shfl_xor_sync(0xffffffffu, a6, o);
        a7 += __shfl_xor_sync(0xffffffffu, a7, o);
    }
    if (sub == 0) {
        float4* ao = agg + (long)node * 16 + 2 * chunk;
        ao[0] = make_float4(a0, a1, a2, a3);
        ao[1] = make_float4(a4, a5, a6, a7);
    }
}

// ---------------------------------------------------------------------------
// GEMM: y = relu((agg * rsqrt(deg_in)) @ W + b)
// fp16 mirror epilogue writes y * rsqrt(deg_out) when xh_out != null.
// When clear != 0 (last layer): zero this block's deg ranges + status
// (replacing the separate zero_tail launch).
__global__ void __launch_bounds__(256)
gemm_kernel(const float* __restrict__ agg, int* __restrict__ deg_in,
            int* __restrict__ deg_out, unsigned* __restrict__ status,
            const float* __restrict__ W, const float* __restrict__ b,
            float* __restrict__ cat_out, float* __restrict__ pool_out,
            __half2* __restrict__ xh_out, int clear, int ntiles, int n) {
    __shared__ float  xs_t[D * XT_STRIDE];
    __shared__ float4 Ws4[D * 16];
    __shared__ float  bs[D];

    int tid  = threadIdx.x;
    int base = blockIdx.x * NPB;

    const float4* W4 = reinterpret_cast<const float4*>(W);
    #pragma unroll
    for (int r = 0; r < 4; ++r)
        Ws4[tid + 256 * r] = W4[tid + 256 * r];
    if (tid < D) bs[tid] = b[tid];

    {
        int node = base + (tid >> 2);
        int k16  = tid & 3;
        if (node < n) {
            float si = rsqrtf((float)max(__ldg(&deg_in[node]), 1));
            const float4* af = reinterpret_cast<const float4*>(agg) + (long)node * 16;
            #pragma unroll
            for (int i = 0; i < 4; ++i) {
                float4 v = af[k16 * 4 + i];
                int k = k16 * 16 + i * 4;
                xs_t[(k + 0) * XT_STRIDE + (node - base)] = v.x * si;
                xs_t[(k + 1) * XT_STRIDE + (node - base)] = v.y * si;
                xs_t[(k + 2) * XT_STRIDE + (node - base)] = v.z * si;
                xs_t[(k + 3) * XT_STRIDE + (node - base)] = v.w * si;
            }
        }
    }
    __syncthreads();

    // Last layer: staging done, deg arrays no longer needed -> zero for next
    // replay. (xh_out==null on the clear layer, so deg_out is unread here.)
    if (clear) {
        if (tid < NPB) {
            int node = base + tid;
            if (node < n) { deg_in[node] = 0; deg_out[node] = 0; }
        }
        if (blockIdx.x == 0 && tid < ntiles) status[tid] = 0u;
    }

    int c4 = tid & 15;
    int ng = tid >> 4;

    u64 acc[4][2];
    {
        u64 blo = pk2(bs[4 * c4 + 0], bs[4 * c4 + 1]);
        u64 bhi = pk2(bs[4 * c4 + 2], bs[4 * c4 + 3]);
        #pragma unroll
        for (int i = 0; i < 4; ++i) { acc[i][0] = blo; acc[i][1] = bhi; }
    }

    #pragma unroll 4
    for (int k = 0; k < D; ++k) {
        float4 w = Ws4[k * 16 + c4];
        u64 wlo = pk2(w.x, w.y);
        u64 whi = pk2(w.z, w.w);
        float4 xv = *reinterpret_cast<const float4*>(&xs_t[k * XT_STRIDE + 4 * ng]);
        u64 x0 = pk2(xv.x, xv.x);
        u64 x1 = pk2(xv.y, xv.y);
        u64 x2 = pk2(xv.z, xv.z);
        u64 x3 = pk2(xv.w, xv.w);
        acc[0][0] = fma2(x0, wlo, acc[0][0]); acc[0][1] = fma2(x0, whi, acc[0][1]);
        acc[1][0] = fma2(x1, wlo, acc[1][0]); acc[1][1] = fma2(x1, whi, acc[1][1]);
        acc[2][0] = fma2(x2, wlo, acc[2][0]); acc[2][1] = fma2(x2, whi, acc[2][1]);
        acc[3][0] = fma2(x3, wlo, acc[3][0]); acc[3][1] = fma2(x3, whi, acc[3][1]);
    }

    float psum[4];
    #pragma unroll
    for (int i = 0; i < 4; ++i) {
        float2 lo = up2(acc[i][0]);
        float2 hi = up2(acc[i][1]);
        float v0 = fmaxf(lo.x, 0.f), v1 = fmaxf(lo.y, 0.f);
        float v2 = fmaxf(hi.x, 0.f), v3 = fmaxf(hi.y, 0.f);
        psum[i] = (v0 + v1) + (v2 + v3);
        int node = base + 4 * ng + i;
        if (node < n) {
            *reinterpret_cast<float4*>(cat_out + (long)node * CAT_STRIDE + 4 * c4)
                = make_float4(v0, v1, v2, v3);
            if (xh_out) {
                float so = rsqrtf((float)max(__ldg(&deg_out[node]), 1));
                xh_out[(long)node * 32 + 2 * c4]     = __floats2half2_rn(v0 * so, v1 * so);
                xh_out[(long)node * 32 + 2 * c4 + 1] = __floats2half2_rn(v2 * so, v3 * so);
            }
        }
    }
    #pragma unroll
    for (int o = 1; o < 16; o <<= 1) {
        #pragma unroll
        for (int i = 0; i < 4; ++i)
            psum[i] += __shfl_xor_sync(0xffffffffu, psum[i], o);
    }
    if (c4 == 0) {
        #pragma unroll
        for (int i = 0; i < 4; ++i) {
            int node = base + 4 * ng + i;
            if (node < n) pool_out[node] = psum[i];
        }
    }
}

// ---------------------------------------------------------------------------
extern "C" void kernel_launch(void* const* d_in, const int* in_sizes, int n_in,
                              void* d_out, int out_size) {
    const float* node_feat = (const float*)d_in[0];
    const int*   src       = (const int*)  d_in[1];
    const int*   dst       = (const int*)  d_in[2];
    const float* W[3] = { (const float*)d_in[4], (const float*)d_in[6], (const float*)d_in[8] };
    const float* B[3] = { (const float*)d_in[5], (const float*)d_in[7], (const float*)d_in[9] };

    const int n = in_sizes[0] / D;
    const int e = in_sizes[1];

    float* out = (float*)d_out;
    float* pool_base = out;                 // [3n]
    float* cat_base  = out + 3 * (long)n;   // [n, 192]

    int *deg_out, *deg_in, *cursor, *csr;
    int2 *rowinfo;
    unsigned* status;
    float* agg;
    __half2* xh;
    cudaGetSymbolAddress((void**)&deg_out, g_deg_out);
    cudaGetSymbolAddress((void**)&deg_in,  g_deg_in);
    cudaGetSymbolAddress((void**)&status,  g_status);
    cudaGetSymbolAddress((void**)&rowinfo, g_rowinfo);
    cudaGetSymbolAddress((void**)&cursor,  g_cursor);
    cudaGetSymbolAddress((void**)&csr,     g_csr);
    cudaGetSymbolAddress((void**)&agg,     g_agg);
    cudaGetSymbolAddress((void**)&xh,      g_xh);

    const int T = 256;
    const int ntiles = (n + STILE - 1) / STILE;
    const int eb = (e + T - 1) / T;
    const int pb = (n * 8 + T - 1) / T;

    // CSR build: deg_count(0) -> scan(1) -> place+prescale(2)
    deg_count_kernel<<<eb, T>>>(src, dst, deg_out, deg_in, e);
    scan_kernel<<<ntiles, T>>>(deg_in, status, rowinfo, cursor, n);
    place_prescale_kernel<<<eb + pb, T>>>(src, dst, cursor, csr, e, eb,
                                          (const float4*)node_feat, deg_out,
                                          (uint4*)xh, n * 8);

    // 3 layers: gather(3,5,7) -> gemm(4,6,8); last gemm clears deg/status
    const int gather_blocks = (n * 32 + T - 1) / T;
    const int gemm_blocks   = (n + NPB - 1) / NPB;

    gather_kernel<<<gather_blocks, T>>>(xh, rowinfo, csr, (float4*)agg, n);
    gemm_kernel<<<gemm_blocks, T>>>(agg, deg_in, deg_out, status, W[0], B[0],
                                    cat_base + 0 * D, pool_base + 0L * n,
                                    xh, 0, ntiles, n);
    gather_kernel<<<gather_blocks, T>>>(xh, rowinfo, csr, (float4*)agg, n);
    gemm_kernel<<<gemm_blocks, T>>>(agg, deg_in, deg_out, status, W[1], B[1],
                                    cat_base + 1 * D, pool_base + 1L * n,
                                    xh, 0, ntiles, n);
    gather_kernel<<<gather_blocks, T>>>(xh, rowinfo, csr, (float4*)agg, n);
    gemm_kernel<<<gemm_blocks, T>>>(agg, deg_in, deg_out, status, W[2], B[2],
                                    cat_base + 2 * D, pool_base + 2L * n,
                                    (__half2*)nullptr, 1, ntiles, n);
}

// round 16
// speedup vs baseline: 1.1611x; 1.0243x over previous
#include <cuda_runtime.h>
#include <cuda_fp16.h>

#define MAX_N 100000
#define MAX_E 1600000
#define D 64
#define CAT_STRIDE 192  // 3*D
#define STILE 1024
#define MAX_TILES ((MAX_N + STILE - 1) / STILE)
#define NPB 64
#define XT_STRIDE 68

typedef unsigned long long u64;

// Scratch (device globals; zero-initialized at load; deg/status re-zeroed by
// the final gemm each replay; everything else fully overwritten per replay)
__device__ int      g_deg_out[MAX_N];
__device__ int      g_deg_in[MAX_N];
__device__ unsigned g_status[MAX_TILES];
__device__ int2     g_rowinfo[MAX_N];    // (row start, deg_in)
__device__ int      g_cursor[MAX_N];
__device__ int      g_csr[MAX_E];        // plain src index
__device__ float    g_agg[MAX_N * D];
__device__ __half2  g_xh[MAX_N * 32];    // fp16 mirror, PRE-SCALED by inv_out

// ---------------------------------------------------------------------------
// f32x2 packed helpers (sm_10x)
__device__ __forceinline__ u64 pk2(float a, float b) {
    u64 r; asm("mov.b64 %0, {%1, %2};" : "=l"(r) : "f"(a), "f"(b)); return r;
}
__device__ __forceinline__ u64 fma2(u64 a, u64 b, u64 c) {
    u64 d; asm("fma.rn.f32x2 %0, %1, %2, %3;" : "=l"(d) : "l"(a), "l"(b), "l"(c)); return d;
}
__device__ __forceinline__ float2 up2(u64 a) {
    float2 f; asm("mov.b64 {%0, %1}, %2;" : "=f"(f.x), "=f"(f.y) : "l"(a)); return f;
}

__device__ __forceinline__ void pdl_sync() {
#if __CUDA_ARCH__ >= 900
    cudaGridDependencySynchronize();
#endif
}
__device__ __forceinline__ void pdl_trigger() {
#if __CUDA_ARCH__ >= 900
    cudaTriggerProgrammaticLaunchCompletion();
#endif
}

// ---------------------------------------------------------------------------
// Count both degrees in one edge pass. (first kernel — no PDL sync needed)
__global__ void deg_count_kernel(const int* __restrict__ src, const int* __restrict__ dst,
                                 int* __restrict__ dout, int* __restrict__ din, int e) {
    int i = blockIdx.x * blockDim.x + threadIdx.x;
    if (i < e) {
        atomicAdd(&dout[src[i]], 1);
        atomicAdd(&din[dst[i]], 1);
    }
}

// Single-pass scan with decoupled lookback (98 tiles < 148 SMs -> all resident).
__global__ void __launch_bounds__(256)
scan_kernel(const int* __restrict__ deg, unsigned* __restrict__ status,
            int2* __restrict__ rowinfo, int* __restrict__ cursor, int n) {
    __shared__ int wsums[8];
    __shared__ int s_excl;

    int tid = threadIdx.x, lane = tid & 31, w = tid >> 5;
    int base = blockIdx.x * STILE + tid * 4;

    pdl_sync();   // wait for deg_count

    int d0 = 0, d1 = 0, d2 = 0, d3 = 0;
    if (base + 3 < n) {
        int4 v = *reinterpret_cast<const int4*>(deg + base);
        d0 = v.x; d1 = v.y; d2 = v.z; d3 = v.w;
    } else {
        if (base + 0 < n) d0 = deg[base + 0];
        if (base + 1 < n) d1 = deg[base + 1];
        if (base + 2 < n) d2 = deg[base + 2];
        if (base + 3 < n) d3 = deg[base + 3];
    }
    int s = d0 + d1 + d2 + d3;

    int inc = s;
    #pragma unroll
    for (int o = 1; o < 32; o <<= 1) {
        int t = __shfl_up_sync(0xffffffffu, inc, o);
        if (lane >= o) inc += t;
    }
    if (lane == 31) wsums[w] = inc;
    __syncthreads();
    if (w == 0 && lane < 8) {
        int t = wsums[lane];
        #pragma unroll
        for (int o = 1; o < 8; o <<= 1) {
            int u = __shfl_up_sync(0xffu, t, o);
            if (lane >= o) t += u;
        }
        wsums[lane] = t;
    }
    __syncthreads();
    int local_excl  = (inc - s) + (w > 0 ? wsums[w - 1] : 0);
    int block_total = wsums[7];

    if (w == 0) {
        volatile unsigned* vst = status;
        if (blockIdx.x == 0) {
            if (lane == 0) {
                vst[0] = 0x80000000u | (unsigned)block_total;
                s_excl = 0;
            }
        } else {
            if (lane == 0) vst[blockIdx.x] = 0x40000000u | (unsigned)block_total;
            int acc = 0;
            int t_hi = blockIdx.x - 1;
            bool done = false;
            while (!done) {
                int idx = t_hi - lane;
                unsigned sv;
                do {
                    sv = (idx >= 0) ? vst[idx] : 0x80000000u;
                } while (__any_sync(0xffffffffu, (sv >> 30) == 0));
                unsigned pm = __ballot_sync(0xffffffffu, (sv >> 30) == 2u);
                int val = (int)(sv & 0x3FFFFFFFu);
                int take;
                if (pm) {
                    int plane = __ffs(pm) - 1;
                    take = (lane <= plane) ? val : 0;
                    done = true;
                } else {
                    take = (idx >= 0) ? val : 0;
                    t_hi -= 32;
                }
                #pragma unroll
                for (int o = 16; o; o >>= 1)
                    take += __shfl_xor_sync(0xffffffffu, take, o);
                acc += take;
            }
            if (lane == 0) {
                vst[blockIdx.x] = 0x80000000u | (unsigned)(acc + block_total);
                s_excl = acc;
            }
        }
    }
    __syncthreads();

    int run = s_excl + local_excl;
    if (base + 3 < n) {
        int r0 = run, r1 = r0 + d0, r2 = r1 + d1, r3 = r2 + d2;
        int4* ri = reinterpret_cast<int4*>(rowinfo + base);
        ri[0] = make_int4(r0, d0, r1, d1);
        ri[1] = make_int4(r2, d2, r3, d3);
        *reinterpret_cast<int4*>(cursor + base) = make_int4(r0, r1, r2, r3);
    } else {
        int d[4] = { d0, d1, d2, d3 };
        for (int jj = 0; jj < 4; ++jj) {
            int i = base + jj;
            if (i < n) { rowinfo[i] = make_int2(run, d[jj]); cursor[i] = run; }
            run += d[jj];
        }
    }
}

// Merged place + prescale: first eb blocks place edges into CSR slots,
// remaining blocks prescale node_feat into the fp16 mirror.
__global__ void __launch_bounds__(256)
place_prescale_kernel(const int* __restrict__ src, const int* __restrict__ dst,
                      int* __restrict__ cursor, int* __restrict__ csr, int e, int eb,
                      const float4* __restrict__ x, const int* __restrict__ deg_out,
                      uint4* __restrict__ xh, int m8) {
    pdl_sync();   // wait for scan (transitively: deg_count)
    int bid = blockIdx.x;
    if (bid < eb) {
        int i = bid * blockDim.x + threadIdx.x;
        if (i < e) {
            int p = atomicAdd(&cursor[dst[i]], 1);
            csr[p] = src[i];
        }
    } else {
        int i = (bid - eb) * blockDim.x + threadIdx.x;  // one 8-float group / thread
        if (i < m8) {
            int node = i >> 3;
            float so = rsqrtf((float)max(__ldg(&deg_out[node]), 1));
            float4 v0 = x[2 * i];
            float4 v1 = x[2 * i + 1];
            __half2 h0 = __floats2half2_rn(v0.x * so, v0.y * so);
            __half2 h1 = __floats2half2_rn(v0.z * so, v0.w * so);
            __half2 h2 = __floats2half2_rn(v1.x * so, v1.y * so);
            __half2 h3 = __floats2half2_rn(v1.z * so, v1.w * so);
            uint4 o;
            o.x = *reinterpret_cast<unsigned*>(&h0);
            o.y = *reinterpret_cast<unsigned*>(&h1);
            o.z = *reinterpret_cast<unsigned*>(&h2);
            o.w = *reinterpret_cast<unsigned*>(&h3);
            xh[i] = o;
        }
    }
}

// ---------------------------------------------------------------------------
// Gather: one warp per node; 4 edges per warp-instruction group.
// 8-edge unroll with pairwise fp16 adds; __launch_bounds__(256,8) caps regs
// at 32 so occupancy stays full.
__global__ void __launch_bounds__(256, 8)
gather_kernel(const __half2* __restrict__ xh,
              const int2* __restrict__ rowinfo,
              const int* __restrict__ csr,
              float4* __restrict__ agg, int n) {
    int node = (blockIdx.x * blockDim.x + threadIdx.x) >> 5;
    int lane = threadIdx.x & 31;

    pdl_sync();   // wait for prev gemm (xh) / place_prescale (csr, xh)

    if (node >= n) return;

    int sub   = lane >> 3;
    int chunk = lane & 7;

    int2 ri   = rowinfo[node];
    int  j    = ri.x;
    int  rend = ri.x + ri.y;

    const uint4* __restrict__ xv = reinterpret_cast<const uint4*>(xh);

    float a0 = 0.f, a1 = 0.f, a2 = 0.f, a3 = 0.f;
    float a4 = 0.f, a5 = 0.f, a6 = 0.f, a7 = 0.f;

    auto accum = [&](uint4 d) {
        float2 f0 = __half22float2(*reinterpret_cast<__half2*>(&d.x));
        float2 f1 = __half22float2(*reinterpret_cast<__half2*>(&d.y));
        float2 f2 = __half22float2(*reinterpret_cast<__half2*>(&d.z));
        float2 f3 = __half22float2(*reinterpret_cast<__half2*>(&d.w));
        a0 += f0.x; a1 += f0.y;
        a2 += f1.x; a3 += f1.y;
        a4 += f2.x; a5 += f2.y;
        a6 += f3.x; a7 += f3.y;
    };
    auto accum2 = [&](uint4 da, uint4 db) {
        __half2 s0 = __hadd2(*reinterpret_cast<__half2*>(&da.x),
                             *reinterpret_cast<__half2*>(&db.x));
        __half2 s1 = __hadd2(*reinterpret_cast<__half2*>(&da.y),
                             *reinterpret_cast<__half2*>(&db.y));
        __half2 s2 = __hadd2(*reinterpret_cast<__half2*>(&da.z),
                             *reinterpret_cast<__half2*>(&db.z));
        __half2 s3 = __hadd2(*reinterpret_cast<__half2*>(&da.w),
                             *reinterpret_cast<__half2*>(&db.w));
        float2 f0 = __half22float2(s0);
        float2 f1 = __half22float2(s1);
        float2 f2 = __half22float2(s2);
        float2 f3 = __half22float2(s3);
        a0 += f0.x; a1 += f0.y;
        a2 += f1.x; a3 += f1.y;
        a4 += f2.x; a5 += f2.y;
        a6 += f3.x; a7 += f3.y;
    };

    for (; j + 8 <= rend; j += 8) {
        int s0 = csr[j + sub];
        int s1 = csr[j + 4 + sub];
        uint4 d0 = xv[(long)s0 * 8 + chunk];
        uint4 d1 = xv[(long)s1 * 8 + chunk];
        accum2(d0, d1);
    }
    for (; j < rend; j += 4) {
        int ei = j + sub;
        if (ei < rend) {
            int s = csr[ei];
            uint4 d = xv[(long)s * 8 + chunk];
            accum(d);
        }
    }

    #pragma unroll
    for (int o = 8; o <= 16; o <<= 1) {
        a0 += __shfl_xor_sync(0xffffffffu, a0, o);
        a1 += __shfl_xor_sync(0xffffffffu, a1, o);
        a2 += __shfl_xor_sync(0xffffffffu, a2, o);
        a3 += __shfl_xor_sync(0xffffffffu, a3, o);
        a4 += __shfl_xor_sync(0xffffffffu, a4, o);
        a5 += __shfl_xor_sync(0xffffffffu, a5, o);
        a6 += __shfl_xor_sync(0xffffffffu, a6, o);
        a7 += __shfl_xor_sync(0xffffffffu, a7, o);
    }
    if (sub == 0) {
        float4* ao = agg + (long)node * 16 + 2 * chunk;
        ao[0] = make_float4(a0, a1, a2, a3);
        ao[1] = make_float4(a4, a5, a6, a7);
    }
}

// ---------------------------------------------------------------------------
// GEMM: y = relu((agg * rsqrt(deg_in)) @ W + b)
// PDL: stages W/b pre-sync (pure inputs), triggers after xh stores.
__global__ void __launch_bounds__(256)
gemm_kernel(const float* __restrict__ agg, int* __restrict__ deg_in,
            int* __restrict__ deg_out, unsigned* __restrict__ status,
            const float* __restrict__ W, const float* __restrict__ b,
            float* __restrict__ cat_out, float* __restrict__ pool_out,
            __half2* __restrict__ xh_out, int clear, int ntiles, int n) {
    __shared__ float  xs_t[D * XT_STRIDE];
    __shared__ float4 Ws4[D * 16];
    __shared__ float  bs[D];

    int tid  = threadIdx.x;
    int base = blockIdx.x * NPB;

    // PRE-SYNC: W and b are harness inputs (never written by kernels) — safe
    // to stage while the previous gather is still finishing.
    const float4* W4 = reinterpret_cast<const float4*>(W);
    #pragma unroll
    for (int r = 0; r < 4; ++r)
        Ws4[tid + 256 * r] = W4[tid + 256 * r];
    if (tid < D) bs[tid] = b[tid];

    pdl_sync();   // wait for gather (agg)

    {
        int node = base + (tid >> 2);
        int k16  = tid & 3;
        if (node < n) {
            float si = rsqrtf((float)max(__ldg(&deg_in[node]), 1));
            const float4* af = reinterpret_cast<const float4*>(agg) + (long)node * 16;
            #pragma unroll
            for (int i = 0; i < 4; ++i) {
                float4 v = af[k16 * 4 + i];
                int k = k16 * 16 + i * 4;
                xs_t[(k + 0) * XT_STRIDE + (node - base)] = v.x * si;
                xs_t[(k + 1) * XT_STRIDE + (node - base)] = v.y * si;
                xs_t[(k + 2) * XT_STRIDE + (node - base)] = v.z * si;
                xs_t[(k + 3) * XT_STRIDE + (node - base)] = v.w * si;
            }
        }
    }
    __syncthreads();

    // Last layer: deg arrays no longer needed -> zero for next replay.
    if (clear) {
        if (tid < NPB) {
            int node = base + tid;
            if (node < n) { deg_in[node] = 0; deg_out[node] = 0; }
        }
        if (blockIdx.x == 0 && tid < ntiles) status[tid] = 0u;
    }

    int c4 = tid & 15;
    int ng = tid >> 4;

    u64 acc[4][2];
    {
        u64 blo = pk2(bs[4 * c4 + 0], bs[4 * c4 + 1]);
        u64 bhi = pk2(bs[4 * c4 + 2], bs[4 * c4 + 3]);
        #pragma unroll
        for (int i = 0; i < 4; ++i) { acc[i][0] = blo; acc[i][1] = bhi; }
    }

    #pragma unroll 4
    for (int k = 0; k < D; ++k) {
        float4 w = Ws4[k * 16 + c4];
        u64 wlo = pk2(w.x, w.y);
        u64 whi = pk2(w.z, w.w);
        float4 xv = *reinterpret_cast<const float4*>(&xs_t[k * XT_STRIDE + 4 * ng]);
        u64 x0 = pk2(xv.x, xv.x);
        u64 x1 = pk2(xv.y, xv.y);
        u64 x2 = pk2(xv.z, xv.z);
        u64 x3 = pk2(xv.w, xv.w);
        acc[0][0] = fma2(x0, wlo, acc[0][0]); acc[0][1] = fma2(x0, whi, acc[0][1]);
        acc[1][0] = fma2(x1, wlo, acc[1][0]); acc[1][1] = fma2(x1, whi, acc[1][1]);
        acc[2][0] = fma2(x2, wlo, acc[2][0]); acc[2][1] = fma2(x2, whi, acc[2][1]);
        acc[3][0] = fma2(x3, wlo, acc[3][0]); acc[3][1] = fma2(x3, whi, acc[3][1]);
    }

    float psum[4];
    #pragma unroll
    for (int i = 0; i < 4; ++i) {
        float2 lo = up2(acc[i][0]);
        float2 hi = up2(acc[i][1]);
        float v0 = fmaxf(lo.x, 0.f), v1 = fmaxf(lo.y, 0.f);
        float v2 = fmaxf(hi.x, 0.f), v3 = fmaxf(hi.y, 0.f);
        psum[i] = (v0 + v1) + (v2 + v3);
        int node = base + 4 * ng + i;
        if (node < n) {
            *reinterpret_cast<float4*>(cat_out + (long)node * CAT_STRIDE + 4 * c4)
                = make_float4(v0, v1, v2, v3);
            if (xh_out) {
                float so = rsqrtf((float)max(__ldg(&deg_out[node]), 1));
                xh_out[(long)node * 32 + 2 * c4]     = __floats2half2_rn(v0 * so, v1 * so);
                xh_out[(long)node * 32 + 2 * c4 + 1] = __floats2half2_rn(v2 * so, v3 * so);
            }
        }
    }

    // xh (the only data the next kernel consumes) is written -> let the next
    // gather start launching while we finish the pool reduction.
    pdl_trigger();

    #pragma unroll
    for (int o = 1; o < 16; o <<= 1) {
        #pragma unroll
        for (int i = 0; i < 4; ++i)
            psum[i] += __shfl_xor_sync(0xffffffffu, psum[i], o);
    }
    if (c4 == 0) {
        #pragma unroll
        for (int i = 0; i < 4; ++i) {
            int node = base + 4 * ng + i;
            if (node < n) pool_out[node] = psum[i];
        }
    }
}

// ---------------------------------------------------------------------------
extern "C" void kernel_launch(void* const* d_in, const int* in_sizes, int n_in,
                              void* d_out, int out_size) {
    const float* node_feat = (const float*)d_in[0];
    const int*   src       = (const int*)  d_in[1];
    const int*   dst       = (const int*)  d_in[2];
    const float* W[3] = { (const float*)d_in[4], (const float*)d_in[6], (const float*)d_in[8] };
    const float* B[3] = { (const float*)d_in[5], (const float*)d_in[7], (const float*)d_in[9] };

    const int n = in_sizes[0] / D;
    const int e = in_sizes[1];

    float* out = (float*)d_out;
    float* pool_base = out;                 // [3n]
    float* cat_base  = out + 3 * (long)n;   // [n, 192]

    int *deg_out, *deg_in, *cursor, *csr;
    int2 *rowinfo;
    unsigned* status;
    float* agg;
    __half2* xh;
    cudaGetSymbolAddress((void**)&deg_out, g_deg_out);
    cudaGetSymbolAddress((void**)&deg_in,  g_deg_in);
    cudaGetSymbolAddress((void**)&status,  g_status);
    cudaGetSymbolAddress((void**)&rowinfo, g_rowinfo);
    cudaGetSymbolAddress((void**)&cursor,  g_cursor);
    cudaGetSymbolAddress((void**)&csr,     g_csr);
    cudaGetSymbolAddress((void**)&agg,     g_agg);
    cudaGetSymbolAddress((void**)&xh,      g_xh);

    const int T = 256;
    const int ntiles = (n + STILE - 1) / STILE;
    const int eb = (e + T - 1) / T;
    const int pb = (n * 8 + T - 1) / T;
    const int gather_blocks = (n * 32 + T - 1) / T;
    const int gemm_blocks   = (n + NPB - 1) / NPB;

    // PDL launch config (reused; attrs copied at launch)
    cudaLaunchAttribute pdl_attr[1];
    pdl_attr[0].id = cudaLaunchAttributeProgrammaticStreamSerialization;
    pdl_attr[0].val.programmaticStreamSerializationAllowed = 1;
    cudaLaunchConfig_t cfg = {};
    cfg.blockDim = dim3(T, 1, 1);
    cfg.stream = 0;
    cfg.attrs = pdl_attr;
    cfg.numAttrs = 1;

    // 0: deg_count (plain launch)
    deg_count_kernel<<<eb, T>>>(src, dst, deg_out, deg_in, e);

    // 1: scan (PDL)
    cfg.gridDim = dim3(ntiles, 1, 1);
    cudaLaunchKernelEx(&cfg, scan_kernel,
                       (const int*)deg_in, status, rowinfo, cursor, n);

    // 2: place + prescale (PDL)
    cfg.gridDim = dim3(eb + pb, 1, 1);
    cudaLaunchKernelEx(&cfg, place_prescale_kernel,
                       src, dst, cursor, csr, e, eb,
                       (const float4*)node_feat, (const int*)deg_out,
                       (uint4*)xh, n * 8);

    // 3..8: gather/gemm x3 (PDL)
    for (int l = 0; l < 3; ++l) {
        cfg.gridDim = dim3(gather_blocks, 1, 1);
        cudaLaunchKernelEx(&cfg, gather_kernel,
                           (const __half2*)xh, (const int2*)rowinfo,
                           (const int*)csr, (float4*)agg, n);

        cfg.gridDim = dim3(gemm_blocks, 1, 1);
        cudaLaunchKernelEx(&cfg, gemm_kernel,
                           (const float*)agg, deg_in, deg_out, status,
                           W[l], B[l],
                           cat_base + l * D, pool_base + (long)l * n,
                           (l < 2) ? xh : (__half2*)nullptr,
                           (l == 2) ? 1 : 0, ntiles, n);
    }
}